// round 5
// baseline (speedup 1.0000x reference)
#include <cuda_runtime.h>

#define KSZ   5
#define CIN   3
#define BATCH 2
#define HH    48
#define KN    16
#define OH    44
#define PP    1936            // OH*OH
#define IMG_ELEMS (CIN*HH*HH) // 6912
#define WSZ   (CIN*KSZ*KSZ)   // 75

#define TILE 128
#define QP2  (PP / 8)         // 242 pairs of float4 per row

typedef unsigned long long u64;

// 30 MB scratch for the unscaled Gram matrix xxT[b, p, q]
__device__ float g_xxT[(size_t)BATCH * PP * PP];

__device__ __forceinline__ u64 pack2(float lo, float hi) {
    u64 r; asm("mov.b64 %0, {%1,%2};" : "=l"(r) : "f"(lo), "f"(hi)); return r;
}
__device__ __forceinline__ void fma2(u64 &d, u64 a, u64 b) {
    asm("fma.rn.f32x2 %0, %1, %2, %0;" : "+l"(d) : "l"(a), "l"(b));
}
__device__ __forceinline__ float2 unpack2(u64 v) {
    float2 f; asm("mov.b64 {%0,%1}, %2;" : "=f"(f.x), "=f"(f.y) : "l"(v)); return f;
}

// ---------------------------------------------------------------------------
// Kernel A: xxT[b,p,q] = sum_f xm[b,p,f] * xm[b,q,f]   (+ fused mu conv)
// Grid (16, 17, 2): blockIdx.y < 16 -> Gram tiles; blockIdx.y == 16 -> the
// mean-path conv (blockIdx.x selects the kn plane), all from SMEM image.
// ---------------------------------------------------------------------------
__global__ __launch_bounds__(256, 2)
void vdp_gram_kernel(const float* __restrict__ mu_in,
                     const float* __restrict__ w_mu,
                     float* __restrict__ mu_out)
{
    __shared__ float img[IMG_ELEMS];
    __shared__ float wgt[WSZ];

    const int tid = threadIdx.x;
    const int b   = blockIdx.z;

    // Load per-batch image (27.6 KB) into SMEM
    const float* src = mu_in + b * IMG_ELEMS;
    for (int i = tid; i < IMG_ELEMS; i += 256) img[i] = src[i];

    if (blockIdx.y == 16) {
        // ---------------- mean conv: this block = one kn plane ----------------
        const int kn = blockIdx.x;
        if (tid < WSZ) wgt[tid] = w_mu[kn * WSZ + tid];
        __syncthreads();

        float* outp = mu_out + ((size_t)b * KN + kn) * (OH * OH);
        #pragma unroll
        for (int k = 0; k < 8; k++) {
            int pos = tid + k * 256;
            if (pos >= OH * OH) break;
            int oy = pos / OH, ox = pos - oy * OH;
            float acc = 0.0f;
            #pragma unroll
            for (int c = 0; c < CIN; c++)
                #pragma unroll
                for (int i = 0; i < KSZ; i++)
                    #pragma unroll
                    for (int j = 0; j < KSZ; j++)
                        acc = fmaf(img[c * HH * HH + (oy + i) * HH + ox + j],
                                   wgt[c * KSZ * KSZ + i * KSZ + j], acc);
            outp[pos] = acc;
        }
        return;
    }
    __syncthreads();

    // ---------------- Gram tile: 128x128, 8x8 microtile -----------------------
    const int tx = tid & 15;
    const int ty = tid >> 4;
    const int p0 = blockIdx.y * TILE;
    const int q0 = blockIdx.x * TILE;

    int basep[8], baseq[8];
    #pragma unroll
    for (int r = 0; r < 8; r++) {
        int p = p0 + ty * 8 + r;
        int pc = (p < PP) ? p : 0;
        int ph = pc / OH, pw = pc - ph * OH;
        basep[r] = ph * HH + pw;
    }
    #pragma unroll
    for (int s = 0; s < 8; s++) {
        int q = q0 + tx + s * 16;
        int qc = (q < PP) ? q : 0;
        int qh = qc / OH, qw = qc - qh * OH;
        baseq[s] = qh * HH + qw;
    }

    u64 acc[8][4];
    #pragma unroll
    for (int r = 0; r < 8; r++)
        #pragma unroll
        for (int h = 0; h < 4; h++) acc[r][h] = 0ULL;

    #pragma unroll 1
    for (int c = 0; c < CIN; c++) {
        int bp[8], bq[8];
        const int coff = c * (HH * HH);
        #pragma unroll
        for (int r = 0; r < 8; r++) bp[r] = basep[r] + coff;
        #pragma unroll
        for (int s = 0; s < 8; s++) bq[s] = baseq[s] + coff;

        #pragma unroll
        for (int i = 0; i < KSZ; i++) {
            #pragma unroll
            for (int j = 0; j < KSZ; j++) {
                const int off = i * HH + j;
                float av[8], bv[8];
                #pragma unroll
                for (int r = 0; r < 8; r++) av[r] = img[bp[r] + off];
                #pragma unroll
                for (int s = 0; s < 8; s++) bv[s] = img[bq[s] + off];

                u64 avp[8], bvp[4];
                #pragma unroll
                for (int r = 0; r < 8; r++) avp[r] = pack2(av[r], av[r]);
                #pragma unroll
                for (int h = 0; h < 4; h++) bvp[h] = pack2(bv[2*h], bv[2*h+1]);

                #pragma unroll
                for (int r = 0; r < 8; r++)
                    #pragma unroll
                    for (int h = 0; h < 4; h++)
                        fma2(acc[r][h], avp[r], bvp[h]);
            }
        }
    }

    // Epilogue: scalar stores of the unscaled Gram tile (30 MB total)
    float* gbase = g_xxT + (size_t)b * PP * PP;
    #pragma unroll
    for (int r = 0; r < 8; r++) {
        int p = p0 + ty * 8 + r;
        if (p >= PP) continue;
        float* row = gbase + (size_t)p * PP;
        #pragma unroll
        for (int h = 0; h < 4; h++) {
            float2 f = unpack2(acc[r][h]);
            int q1 = q0 + tx + 32 * h;
            int q2 = q1 + 16;
            if (q1 < PP) row[q1] = f.x;
            if (q2 < PP) row[q2] = f.y;
        }
    }
}

// ---------------------------------------------------------------------------
// Kernel B: sigma[b,kn,p,q] = xxT[b,p,q] * softplus(w_sigma[kn])
// Each thread: 2 consecutive float4 (32B) -> 16 planes x 2 STG.128 streaming.
// Warp writes 1 KB contiguous per plane.
// ---------------------------------------------------------------------------
__global__ __launch_bounds__(256)
void vdp_scale_kernel(const float* __restrict__ w_sigma,
                      float* __restrict__ sigma)
{
    __shared__ float sp[KN];
    if (threadIdx.x < KN) sp[threadIdx.x] = log1pf(expf(w_sigma[threadIdx.x]));
    __syncthreads();

    int idx = blockIdx.x * 256 + threadIdx.x;
    const int total = BATCH * PP * QP2;
    if (idx >= total) return;

    int qp = idx % QP2;
    int p  = (idx / QP2) % PP;
    int b  = idx / (QP2 * PP);

    const float* gsrc = &g_xxT[((size_t)b * PP + p) * PP + qp * 8];
    const float4 v0 = __ldcg((const float4*)gsrc);
    const float4 v1 = __ldcg((const float4*)(gsrc + 4));

    const size_t planeStride = (size_t)PP * PP;
    float* o = sigma + ((size_t)b * KN) * planeStride + (size_t)p * PP + qp * 8;

    #pragma unroll
    for (int kn = 0; kn < KN; kn++) {
        const float s = sp[kn];
        float4 w0, w1;
        w0.x = v0.x * s; w0.y = v0.y * s; w0.z = v0.z * s; w0.w = v0.w * s;
        w1.x = v1.x * s; w1.y = v1.y * s; w1.z = v1.z * s; w1.w = v1.w * s;
        __stcs((float4*)o, w0);
        __stcs((float4*)(o + 4), w1);
        o += planeStride;
    }
}

extern "C" void kernel_launch(void* const* d_in, const int* in_sizes, int n_in,
                              void* d_out, int out_size)
{
    const float* mu_in   = (const float*)d_in[0];
    const float* w_mu    = (const float*)d_in[1];
    const float* w_sigma = (const float*)d_in[2];

    float* out    = (float*)d_out;
    float* mu_out = out;
    float* sigma  = out + (size_t)BATCH * KN * OH * OH;

    dim3 gridA(16, 17, BATCH);   // y==16 row handles the mu conv (x = kn)
    vdp_gram_kernel<<<gridA, 256>>>(mu_in, w_mu, mu_out);

    const int totalB = BATCH * PP * QP2;   // 937,024
    vdp_scale_kernel<<<(totalB + 255) / 256, 256>>>(w_sigma, sigma);
}

// round 6
// speedup vs baseline: 1.4944x; 1.4944x over previous
#include <cuda_runtime.h>

#define KSZ   5
#define CIN   3
#define BATCH 2
#define HH    48
#define KN    16
#define OH    44
#define PP    1936            // OH*OH
#define IMG_ELEMS (CIN*HH*HH) // 6912
#define WSZ   (CIN*KSZ*KSZ)   // 75

#define TILE 128
#define QV   (PP / 4)         // 484 float4 per row

typedef unsigned long long u64;

// 30 MB scratch for the unscaled Gram matrix xxT[b, p, q]
__device__ float g_xxT[(size_t)BATCH * PP * PP];

__device__ __forceinline__ u64 pack2(float lo, float hi) {
    u64 r; asm("mov.b64 %0, {%1,%2};" : "=l"(r) : "f"(lo), "f"(hi)); return r;
}
__device__ __forceinline__ void fma2(u64 &d, u64 a, u64 b) {
    asm("fma.rn.f32x2 %0, %1, %2, %0;" : "+l"(d) : "l"(a), "l"(b));
}
__device__ __forceinline__ float2 unpack2(u64 v) {
    float2 f; asm("mov.b64 {%0,%1}, %2;" : "=f"(f.x), "=f"(f.y) : "l"(v)); return f;
}

// ---------------------------------------------------------------------------
// Kernel A: xxT[b,p,q] = sum_f xm[b,p,f] * xm[b,q,f]   (+ fused mu conv)
// Grid (16, 17, 2): blockIdx.y < 16 -> Gram tiles; blockIdx.y == 16 -> the
// mean-path conv (blockIdx.x selects the kn plane), all from SMEM image.
// ---------------------------------------------------------------------------
__global__ __launch_bounds__(256, 2)
void vdp_gram_kernel(const float* __restrict__ mu_in,
                     const float* __restrict__ w_mu,
                     float* __restrict__ mu_out)
{
    __shared__ float img[IMG_ELEMS];
    __shared__ float wgt[WSZ];

    const int tid = threadIdx.x;
    const int b   = blockIdx.z;

    // Load per-batch image (27.6 KB) into SMEM
    const float* src = mu_in + b * IMG_ELEMS;
    for (int i = tid; i < IMG_ELEMS; i += 256) img[i] = src[i];

    if (blockIdx.y == 16) {
        // ---------------- mean conv: this block = one kn plane ----------------
        const int kn = blockIdx.x;
        if (tid < WSZ) wgt[tid] = w_mu[kn * WSZ + tid];
        __syncthreads();

        float* outp = mu_out + ((size_t)b * KN + kn) * (OH * OH);
        #pragma unroll
        for (int k = 0; k < 8; k++) {
            int pos = tid + k * 256;
            if (pos >= OH * OH) break;
            int oy = pos / OH, ox = pos - oy * OH;
            float acc = 0.0f;
            #pragma unroll
            for (int c = 0; c < CIN; c++)
                #pragma unroll
                for (int i = 0; i < KSZ; i++)
                    #pragma unroll
                    for (int j = 0; j < KSZ; j++)
                        acc = fmaf(img[c * HH * HH + (oy + i) * HH + ox + j],
                                   wgt[c * KSZ * KSZ + i * KSZ + j], acc);
            outp[pos] = acc;
        }
        return;
    }
    __syncthreads();

    // ---------------- Gram tile: 128x128, 8x8 microtile -----------------------
    const int tx = tid & 15;
    const int ty = tid >> 4;
    const int p0 = blockIdx.y * TILE;
    const int q0 = blockIdx.x * TILE;

    int basep[8], baseq[8];
    #pragma unroll
    for (int r = 0; r < 8; r++) {
        int p = p0 + ty * 8 + r;
        int pc = (p < PP) ? p : 0;
        int ph = pc / OH, pw = pc - ph * OH;
        basep[r] = ph * HH + pw;
    }
    #pragma unroll
    for (int s = 0; s < 8; s++) {
        int q = q0 + tx + s * 16;
        int qc = (q < PP) ? q : 0;
        int qh = qc / OH, qw = qc - qh * OH;
        baseq[s] = qh * HH + qw;
    }

    u64 acc[8][4];
    #pragma unroll
    for (int r = 0; r < 8; r++)
        #pragma unroll
        for (int h = 0; h < 4; h++) acc[r][h] = 0ULL;

    #pragma unroll 1
    for (int c = 0; c < CIN; c++) {
        int bp[8], bq[8];
        const int coff = c * (HH * HH);
        #pragma unroll
        for (int r = 0; r < 8; r++) bp[r] = basep[r] + coff;
        #pragma unroll
        for (int s = 0; s < 8; s++) bq[s] = baseq[s] + coff;

        #pragma unroll
        for (int i = 0; i < KSZ; i++) {
            #pragma unroll
            for (int j = 0; j < KSZ; j++) {
                const int off = i * HH + j;
                float av[8], bv[8];
                #pragma unroll
                for (int r = 0; r < 8; r++) av[r] = img[bp[r] + off];
                #pragma unroll
                for (int s = 0; s < 8; s++) bv[s] = img[bq[s] + off];

                u64 avp[8], bvp[4];
                #pragma unroll
                for (int r = 0; r < 8; r++) avp[r] = pack2(av[r], av[r]);
                #pragma unroll
                for (int h = 0; h < 4; h++) bvp[h] = pack2(bv[2*h], bv[2*h+1]);

                #pragma unroll
                for (int r = 0; r < 8; r++)
                    #pragma unroll
                    for (int h = 0; h < 4; h++)
                        fma2(acc[r][h], avp[r], bvp[h]);
            }
        }
    }

    // Epilogue: scalar stores of the unscaled Gram tile (30 MB total)
    float* gbase = g_xxT + (size_t)b * PP * PP;
    #pragma unroll
    for (int r = 0; r < 8; r++) {
        int p = p0 + ty * 8 + r;
        if (p >= PP) continue;
        float* row = gbase + (size_t)p * PP;
        #pragma unroll
        for (int h = 0; h < 4; h++) {
            float2 f = unpack2(acc[r][h]);
            int q1 = q0 + tx + 32 * h;
            int q2 = q1 + 16;
            if (q1 < PP) row[q1] = f.x;
            if (q2 < PP) row[q2] = f.y;
        }
    }
}

// ---------------------------------------------------------------------------
// Kernel B (R4 measured-good config): sigma[b,kn,p,q] = xxT[b,p,q] * sp[kn]
// One float4 per thread; consecutive lanes -> consecutive 16B, so every
// STG.128 is a dense 512B warp footprint. 16 streaming stores per thread.
// ---------------------------------------------------------------------------
__global__ __launch_bounds__(256)
void vdp_scale_kernel(const float* __restrict__ w_sigma,
                      float* __restrict__ sigma)
{
    __shared__ float sp[KN];
    if (threadIdx.x < KN) sp[threadIdx.x] = log1pf(expf(w_sigma[threadIdx.x]));
    __syncthreads();

    int idx = blockIdx.x * 256 + threadIdx.x;
    const int total = BATCH * PP * QV;
    if (idx >= total) return;

    int qv = idx % QV;
    int p  = (idx / QV) % PP;
    int b  = idx / (QV * PP);

    const float4 v = __ldcg((const float4*)&g_xxT[((size_t)b * PP + p) * PP + qv * 4]);

    const size_t planeStride = (size_t)PP * PP;
    float* o = sigma + ((size_t)b * KN) * planeStride + (size_t)p * PP + qv * 4;

    #pragma unroll
    for (int kn = 0; kn < KN; kn++) {
        const float s = sp[kn];
        float4 w;
        w.x = v.x * s; w.y = v.y * s; w.z = v.z * s; w.w = v.w * s;
        __stcs((float4*)o, w);
        o += planeStride;
    }
}

extern "C" void kernel_launch(void* const* d_in, const int* in_sizes, int n_in,
                              void* d_out, int out_size)
{
    const float* mu_in   = (const float*)d_in[0];
    const float* w_mu    = (const float*)d_in[1];
    const float* w_sigma = (const float*)d_in[2];

    float* out    = (float*)d_out;
    float* mu_out = out;
    float* sigma  = out + (size_t)BATCH * KN * OH * OH;

    dim3 gridA(16, 17, BATCH);   // y==16 row handles the mu conv (x = kn)
    vdp_gram_kernel<<<gridA, 256>>>(mu_in, w_mu, mu_out);

    const int totalB = BATCH * PP * QV;   // 1,874,048
    vdp_scale_kernel<<<(totalB + 255) / 256, 256>>>(w_sigma, sigma);
}

// round 7
// speedup vs baseline: 1.6311x; 1.0915x over previous
#include <cuda_runtime.h>

#define KSZ   5
#define CIN   3
#define BATCH 2
#define HH    48
#define KN    16
#define OH    44
#define PP    1936            // OH*OH
#define IMG_ELEMS (CIN*HH*HH) // 6912
#define WSZ   (CIN*KSZ*KSZ)   // 75

#define TILE    128
#define NT      16            // tiles per dim
#define NUPPER  (NT * (NT + 1) / 2)   // 136 upper-triangular tiles
#define QV      (PP / 4)      // 484 float4 per row

typedef unsigned long long u64;

// 30 MB scratch for the unscaled Gram matrix xxT[b, p, q]
__device__ float g_xxT[(size_t)BATCH * PP * PP];

__device__ __forceinline__ u64 pack2(float lo, float hi) {
    u64 r; asm("mov.b64 %0, {%1,%2};" : "=l"(r) : "f"(lo), "f"(hi)); return r;
}
__device__ __forceinline__ void fma2(u64 &d, u64 a, u64 b) {
    asm("fma.rn.f32x2 %0, %1, %2, %0;" : "+l"(d) : "l"(a), "l"(b));
}
__device__ __forceinline__ float2 unpack2(u64 v) {
    float2 f; asm("mov.b64 {%0,%1}, %2;" : "=f"(f.x), "=f"(f.y) : "l"(v)); return f;
}

// ---------------------------------------------------------------------------
// Kernel A: xxT[b,p,q] = sum_f xm[b,p,f] * xm[b,q,f]   (+ fused mu conv)
// Grid (152, 1, 2): x < 136 -> upper-triangular Gram tile (stored twice:
// normal + mirrored); x >= 136 -> mean conv plane kn = x-136.
// ---------------------------------------------------------------------------
__global__ __launch_bounds__(256, 2)
void vdp_gram_kernel(const float* __restrict__ mu_in,
                     const float* __restrict__ w_mu,
                     float* __restrict__ mu_out)
{
    __shared__ float img[IMG_ELEMS];
    __shared__ float wgt[WSZ];

    const int tid = threadIdx.x;
    const int b   = blockIdx.z;

    // Load per-batch image (27.6 KB) into SMEM
    const float* src = mu_in + b * IMG_ELEMS;
    for (int i = tid; i < IMG_ELEMS; i += 256) img[i] = src[i];

    if (blockIdx.x >= NUPPER) {
        // ---------------- mean conv: this block = one kn plane ----------------
        const int kn = blockIdx.x - NUPPER;
        if (tid < WSZ) wgt[tid] = w_mu[kn * WSZ + tid];
        __syncthreads();

        float* outp = mu_out + ((size_t)b * KN + kn) * (OH * OH);
        #pragma unroll
        for (int k = 0; k < 8; k++) {
            int pos = tid + k * 256;
            if (pos >= OH * OH) break;
            int oy = pos / OH, ox = pos - oy * OH;
            float acc = 0.0f;
            #pragma unroll
            for (int c = 0; c < CIN; c++)
                #pragma unroll
                for (int i = 0; i < KSZ; i++)
                    #pragma unroll
                    for (int j = 0; j < KSZ; j++)
                        acc = fmaf(img[c * HH * HH + (oy + i) * HH + ox + j],
                                   wgt[c * KSZ * KSZ + i * KSZ + j], acc);
            outp[pos] = acc;
        }
        return;
    }
    __syncthreads();

    // Map linear tile index -> (ti, tj) with ti <= tj
    int ti = 0, rem = blockIdx.x;
    while (rem >= NT - ti) { rem -= NT - ti; ti++; }
    const int tj = ti + rem;

    const int tx = tid & 15;
    const int ty = tid >> 4;
    const int p0 = ti * TILE;
    const int q0 = tj * TILE;

    int basep[8], baseq[8];
    #pragma unroll
    for (int r = 0; r < 8; r++) {
        int p = p0 + ty * 8 + r;
        int pc = (p < PP) ? p : 0;
        int ph = pc / OH, pw = pc - ph * OH;
        basep[r] = ph * HH + pw;
    }
    #pragma unroll
    for (int s = 0; s < 8; s++) {
        int q = q0 + tx + s * 16;
        int qc = (q < PP) ? q : 0;
        int qh = qc / OH, qw = qc - qh * OH;
        baseq[s] = qh * HH + qw;
    }

    u64 acc[8][4];
    #pragma unroll
    for (int r = 0; r < 8; r++)
        #pragma unroll
        for (int h = 0; h < 4; h++) acc[r][h] = 0ULL;

    #pragma unroll 1
    for (int c = 0; c < CIN; c++) {
        int bp[8], bq[8];
        const int coff = c * (HH * HH);
        #pragma unroll
        for (int r = 0; r < 8; r++) bp[r] = basep[r] + coff;
        #pragma unroll
        for (int s = 0; s < 8; s++) bq[s] = baseq[s] + coff;

        #pragma unroll
        for (int i = 0; i < KSZ; i++) {
            #pragma unroll
            for (int j = 0; j < KSZ; j++) {
                const int off = i * HH + j;
                float av[8], bv[8];
                #pragma unroll
                for (int r = 0; r < 8; r++) av[r] = img[bp[r] + off];
                #pragma unroll
                for (int s = 0; s < 8; s++) bv[s] = img[bq[s] + off];

                u64 avp[8], bvp[4];
                #pragma unroll
                for (int r = 0; r < 8; r++) avp[r] = pack2(av[r], av[r]);
                #pragma unroll
                for (int h = 0; h < 4; h++) bvp[h] = pack2(bv[2*h], bv[2*h+1]);

                #pragma unroll
                for (int r = 0; r < 8; r++)
                    #pragma unroll
                    for (int h = 0; h < 4; h++)
                        fma2(acc[r][h], avp[r], bvp[h]);
            }
        }
    }

    float* gbase = g_xxT + (size_t)b * PP * PP;

    // Normal-orientation store of tile (ti, tj)
    #pragma unroll
    for (int r = 0; r < 8; r++) {
        int p = p0 + ty * 8 + r;
        if (p >= PP) continue;
        float* row = gbase + (size_t)p * PP;
        #pragma unroll
        for (int h = 0; h < 4; h++) {
            float2 f = unpack2(acc[r][h]);
            int q1 = q0 + tx + 32 * h;
            int q2 = q1 + 16;
            if (q1 < PP) row[q1] = f.x;
            if (q2 < PP) row[q2] = f.y;
        }
    }

    // Mirrored store of tile (tj, ti): row q, 8 consecutive p per thread.
    // Per STG.128 the warp covers 16 rows x 32B contiguous -> sector-dense.
    if (ti != tj) {
        const int pbase = p0 + ty * 8;
        #pragma unroll
        for (int s = 0; s < 8; s++) {
            int q = q0 + tx + 16 * s;
            if (q >= PP) continue;
            // val[r] for this s: s even -> .x of acc[r][s/2], odd -> .y
            float4 v0, v1;
            {
                float2 a0 = unpack2(acc[0][s >> 1]);
                float2 a1 = unpack2(acc[1][s >> 1]);
                float2 a2 = unpack2(acc[2][s >> 1]);
                float2 a3 = unpack2(acc[3][s >> 1]);
                float2 a4 = unpack2(acc[4][s >> 1]);
                float2 a5 = unpack2(acc[5][s >> 1]);
                float2 a6 = unpack2(acc[6][s >> 1]);
                float2 a7 = unpack2(acc[7][s >> 1]);
                if (s & 1) {
                    v0 = make_float4(a0.y, a1.y, a2.y, a3.y);
                    v1 = make_float4(a4.y, a5.y, a6.y, a7.y);
                } else {
                    v0 = make_float4(a0.x, a1.x, a2.x, a3.x);
                    v1 = make_float4(a4.x, a5.x, a6.x, a7.x);
                }
            }
            float* row = gbase + (size_t)q * PP + pbase;
            if (pbase < PP)     *(float4*)row       = v0;
            if (pbase + 4 < PP) *(float4*)(row + 4) = v1;
        }
    }
}

// ---------------------------------------------------------------------------
// Kernel B (measured-good config): sigma[b,kn,p,q] = xxT[b,p,q] * sp[kn]
// One float4 per thread; consecutive lanes -> consecutive 16B (dense 512B
// per STG.128). 16 streaming stores per thread.
// ---------------------------------------------------------------------------
__global__ __launch_bounds__(256)
void vdp_scale_kernel(const float* __restrict__ w_sigma,
                      float* __restrict__ sigma)
{
    __shared__ float sp[KN];
    if (threadIdx.x < KN) sp[threadIdx.x] = log1pf(expf(w_sigma[threadIdx.x]));
    __syncthreads();

    int idx = blockIdx.x * 256 + threadIdx.x;
    const int total = BATCH * PP * QV;
    if (idx >= total) return;

    int qv = idx % QV;
    int p  = (idx / QV) % PP;
    int b  = idx / (QV * PP);

    const float4 v = __ldcg((const float4*)&g_xxT[((size_t)b * PP + p) * PP + qv * 4]);

    const size_t planeStride = (size_t)PP * PP;
    float* o = sigma + ((size_t)b * KN) * planeStride + (size_t)p * PP + qv * 4;

    #pragma unroll
    for (int kn = 0; kn < KN; kn++) {
        const float s = sp[kn];
        float4 w;
        w.x = v.x * s; w.y = v.y * s; w.z = v.z * s; w.w = v.w * s;
        __stcs((float4*)o, w);
        o += planeStride;
    }
}

extern "C" void kernel_launch(void* const* d_in, const int* in_sizes, int n_in,
                              void* d_out, int out_size)
{
    const float* mu_in   = (const float*)d_in[0];
    const float* w_mu    = (const float*)d_in[1];
    const float* w_sigma = (const float*)d_in[2];

    float* out    = (float*)d_out;
    float* mu_out = out;
    float* sigma  = out + (size_t)BATCH * KN * OH * OH;

    dim3 gridA(NUPPER + KN, 1, BATCH);   // 136 gram tiles + 16 mu planes, x2 batch
    vdp_gram_kernel<<<gridA, 256>>>(mu_in, w_mu, mu_out);

    const int totalB = BATCH * PP * QV;  // 1,874,048
    vdp_scale_kernel<<<(totalB + 255) / 256, 256>>>(w_sigma, sigma);
}